// round 1
// baseline (speedup 1.0000x reference)
#include <cuda_runtime.h>
#include <cuda_bf16.h>

// IDW interpolation, POWER=2:
//   w = 1/d^2  (sqrt cancels), out[p] = sum(w*v) / sum(w)
// d==0 handling: reference substitutes EPS into the distance, giving a
// gigantic weight that dominates the sum. We fold +1e-30 into d^2 instead:
// same dominating behavior, zero extra instructions, no branch.

#define NSTATIONS 512
#define TPB 256
#define PTS_PER_THREAD 4

__global__ __launch_bounds__(TPB) void idw_kernel(
    const float* __restrict__ station_coords,  // (B, S, 2)
    const float* __restrict__ station_values,  // (B, S)
    const float* __restrict__ grid_points,     // (B, P, 2)
    float* __restrict__ out,                   // (B, P)
    int P, int S)
{
    __shared__ float4 st[NSTATIONS];  // {x, y, value, pad}

    const int b = blockIdx.y;
    const float* sc = station_coords + (size_t)b * S * 2;
    const float* sv = station_values + (size_t)b * S;

    // Stage stations into shared memory (512 * 16B = 8KB)
    for (int s = threadIdx.x; s < S; s += TPB) {
        float2 c = reinterpret_cast<const float2*>(sc)[s];
        st[s] = make_float4(c.x, c.y, sv[s], 0.0f);
    }
    __syncthreads();

    const int base = (blockIdx.x * TPB + threadIdx.x) * PTS_PER_THREAD;

    // Load 4 grid points = 8 floats = 2 x float4 (coalesced, 16B-aligned)
    const float4* gp = reinterpret_cast<const float4*>(
        grid_points + (size_t)b * P * 2 + (size_t)base * 2);
    float4 a0 = gp[0];
    float4 a1 = gp[1];

    float gx[PTS_PER_THREAD], gy[PTS_PER_THREAD];
    gx[0] = a0.x; gy[0] = a0.y;
    gx[1] = a0.z; gy[1] = a0.w;
    gx[2] = a1.x; gy[2] = a1.y;
    gx[3] = a1.z; gy[3] = a1.w;

    float ws[PTS_PER_THREAD], vs[PTS_PER_THREAD];
    #pragma unroll
    for (int i = 0; i < PTS_PER_THREAD; i++) { ws[i] = 0.0f; vs[i] = 0.0f; }

    #pragma unroll 4
    for (int s = 0; s < NSTATIONS; s++) {
        float4 stn = st[s];  // broadcast LDS.128
        #pragma unroll
        for (int i = 0; i < PTS_PER_THREAD; i++) {
            float dx = gx[i] - stn.x;
            float dy = gy[i] - stn.y;
            float d2 = fmaf(dx, dx, fmaf(dy, dy, 1e-30f));
            float w;
            asm("rcp.approx.f32 %0, %1;" : "=f"(w) : "f"(d2));  // one MUFU.RCP
            ws[i] += w;
            vs[i] = fmaf(w, stn.z, vs[i]);
        }
    }

    float4 r;
    r.x = vs[0] / ws[0];
    r.y = vs[1] / ws[1];
    r.z = vs[2] / ws[2];
    r.w = vs[3] / ws[3];
    reinterpret_cast<float4*>(out + (size_t)b * P + base)[0] = r;
}

extern "C" void kernel_launch(void* const* d_in, const int* in_sizes, int n_in,
                              void* d_out, int out_size) {
    const float* station_coords = (const float*)d_in[0];  // (B,S,2)
    const float* station_values = (const float*)d_in[1];  // (B,S)
    const float* grid_points    = (const float*)d_in[2];  // (B,P,2)
    float* out = (float*)d_out;

    const int S = NSTATIONS;                 // 512 per problem spec
    const int B = in_sizes[1] / S;           // 2
    const int P = in_sizes[2] / (B * 2);     // 131072

    dim3 grid(P / (TPB * PTS_PER_THREAD), B);  // (128, 2)
    idw_kernel<<<grid, TPB>>>(station_coords, station_values, grid_points,
                              out, P, S);
}

// round 2
// speedup vs baseline: 1.3812x; 1.3812x over previous
#include <cuda_runtime.h>
#include <cuda_bf16.h>

// IDW interpolation, POWER=2:  w = 1/d^2 (sqrt cancels).
//
// Key optimization vs round 1 (which was MUFU.RCP-bound at rt_SMSP=8):
//   Station pairing: for d2 values a,b of two stations,
//     w1+w2       = (a+b)/(a*b)
//     w1*v1+w2*v2 = (v1*b + v2*a)/(a*b)
//   -> ONE rcp per TWO stations (halves MUFU pressure).
//   Point packing: all FP32 math uses f32x2 packed ops (2 grid points per
//   instruction). Stations are staged in smem pre-DUPLICATED and pre-NEGATED
//   ((-x,-x) as one 8-byte word) so a single LDS.64 yields a ready packed
//   operand (dx sign is irrelevant: it gets squared).
//
// d==0 handling: reference substitutes EPS into the distance -> giant weight
// dominates the sum. We fold +1e-12 into d^2: same dominating behavior, no
// branch, and the pair product a*b can't underflow.

#define NSTATIONS 512
#define TPB 64
#define PTS 4  // grid points per thread = 2 packed f32x2 lanes

typedef unsigned long long u64;

__device__ __forceinline__ u64 f2_pack(float lo, float hi) {
    u64 r; asm("mov.b64 %0, {%1, %2};" : "=l"(r) : "f"(lo), "f"(hi)); return r;
}
__device__ __forceinline__ void f2_unpack(u64 a, float& lo, float& hi) {
    asm("mov.b64 {%0, %1}, %2;" : "=f"(lo), "=f"(hi) : "l"(a));
}
__device__ __forceinline__ u64 f2_add(u64 a, u64 b) {
    u64 r; asm("add.rn.f32x2 %0, %1, %2;" : "=l"(r) : "l"(a), "l"(b)); return r;
}
__device__ __forceinline__ u64 f2_mul(u64 a, u64 b) {
    u64 r; asm("mul.rn.f32x2 %0, %1, %2;" : "=l"(r) : "l"(a), "l"(b)); return r;
}
__device__ __forceinline__ u64 f2_fma(u64 a, u64 b, u64 c) {
    u64 r; asm("fma.rn.f32x2 %0, %1, %2, %3;" : "=l"(r) : "l"(a), "l"(b), "l"(c)); return r;
}
__device__ __forceinline__ float frcp(float a) {
    float r; asm("rcp.approx.f32 %0, %1;" : "=f"(r) : "f"(a)); return r;
}
__device__ __forceinline__ u64 f2_rcp(u64 a) {
    float lo, hi; f2_unpack(a, lo, hi);
    return f2_pack(frcp(lo), frcp(hi));
}

__global__ __launch_bounds__(TPB) void idw_kernel(
    const float* __restrict__ station_coords,  // (B, S, 2)
    const float* __restrict__ station_values,  // (B, S)
    const float* __restrict__ grid_points,     // (B, P, 2)
    float* __restrict__ out,                   // (B, P)
    int P)
{
    // Duplicated/negated station data: one LDS.64 -> packed broadcast operand
    __shared__ u64 sh_nx[NSTATIONS];  // (-x, -x)
    __shared__ u64 sh_ny[NSTATIONS];  // (-y, -y)
    __shared__ u64 sh_vv[NSTATIONS];  // ( v,  v)

    const int base = (blockIdx.x * TPB + threadIdx.x) * PTS;  // global point id
    const int b = base / P;  // PTS*TPB=256 divides P -> no block straddles batches

    const float* sc = station_coords + (size_t)b * NSTATIONS * 2;
    const float* sv = station_values + (size_t)b * NSTATIONS;

    for (int s = threadIdx.x; s < NSTATIONS; s += TPB) {
        float2 c = reinterpret_cast<const float2*>(sc)[s];
        float v = sv[s];
        sh_nx[s] = f2_pack(-c.x, -c.x);
        sh_ny[s] = f2_pack(-c.y, -c.y);
        sh_vv[s] = f2_pack(v, v);
    }
    __syncthreads();

    // Load 4 grid points = 2 x float4 (coalesced)
    const float4* gp = reinterpret_cast<const float4*>(
        grid_points + ((size_t)b * P + (base - b * P)) * 2);
    float4 a0 = gp[0];
    float4 a1 = gp[1];

    u64 gx[2], gy[2];
    gx[0] = f2_pack(a0.x, a0.z);  gy[0] = f2_pack(a0.y, a0.w);
    gx[1] = f2_pack(a1.x, a1.z);  gy[1] = f2_pack(a1.y, a1.w);

    const u64 eps2 = f2_pack(1e-12f, 1e-12f);
    u64 ws[2], vs[2];
    ws[0] = ws[1] = 0ull;  // packed (0.0f, 0.0f)
    vs[0] = vs[1] = 0ull;

    #pragma unroll 4
    for (int s = 0; s < NSTATIONS; s += 2) {
        u64 nx1 = sh_nx[s],     ny1 = sh_ny[s],     v1 = sh_vv[s];
        u64 nx2 = sh_nx[s + 1], ny2 = sh_ny[s + 1], v2 = sh_vv[s + 1];
        #pragma unroll
        for (int q = 0; q < 2; q++) {
            u64 dx1 = f2_add(gx[q], nx1);
            u64 dy1 = f2_add(gy[q], ny1);
            u64 da  = f2_fma(dy1, dy1, eps2);
            da      = f2_fma(dx1, dx1, da);        // a = d2 of station 1
            u64 dx2 = f2_add(gx[q], nx2);
            u64 dy2 = f2_add(gy[q], ny2);
            u64 db  = f2_fma(dy2, dy2, eps2);
            db      = f2_fma(dx2, dx2, db);        // b = d2 of station 2
            u64 sum  = f2_add(da, db);             // a + b
            u64 prod = f2_mul(da, db);             // a * b
            u64 num  = f2_mul(v1, db);
            num      = f2_fma(v2, da, num);        // v1*b + v2*a
            u64 r    = f2_rcp(prod);               // 2x MUFU.RCP (one per 2 stations/pt)
            ws[q] = f2_fma(sum, r, ws[q]);
            vs[q] = f2_fma(num, r, vs[q]);
        }
    }

    float w0, w1h, w2, w3, n0, n1, n2, n3;
    f2_unpack(ws[0], w0, w1h);  f2_unpack(ws[1], w2, w3);
    f2_unpack(vs[0], n0, n1);   f2_unpack(vs[1], n2, n3);

    float4 r;
    r.x = n0 * frcp(w0);
    r.y = n1 * frcp(w1h);
    r.z = n2 * frcp(w2);
    r.w = n3 * frcp(w3);
    reinterpret_cast<float4*>(out + (size_t)base)[0] = r;  // out is (B,P) flat
}

extern "C" void kernel_launch(void* const* d_in, const int* in_sizes, int n_in,
                              void* d_out, int out_size) {
    const float* station_coords = (const float*)d_in[0];  // (B,S,2)
    const float* station_values = (const float*)d_in[1];  // (B,S)
    const float* grid_points    = (const float*)d_in[2];  // (B,P,2)
    float* out = (float*)d_out;

    const int S = NSTATIONS;                 // 512 per problem spec
    const int B = in_sizes[1] / S;           // 2
    const int P = in_sizes[2] / (B * 2);     // 131072

    const int total_points = B * P;                    // 262144
    const int blocks = total_points / (TPB * PTS);     // 1024 -> 6.92 blocks/SM
    idw_kernel<<<blocks, TPB>>>(station_coords, station_values, grid_points,
                                out, P);
}

// round 3
// speedup vs baseline: 1.4952x; 1.0825x over previous
#include <cuda_runtime.h>
#include <cuda_bf16.h>

// IDW interpolation, POWER=2:  w = 1/d^2 (sqrt cancels).
//
// Round 3: same math as round 2 (station pairing -> 1 rcp per 2 stations;
// f32x2 packed ops, 2 grid points per instruction), but PTS 4->2 and
// TPB 64->128 to double resident warps (2048 -> 4096 total, ~6.9/SMSP).
// Round 2 was latency-bound: occ=15.6%, issue=59.7% -- schedulers idle
// half the time waiting on MUFU/LDS chains with only 3.5 warps/SMSP.
//
// Pairing identity for d2 values a,b:
//   w1+w2       = (a+b)/(a*b)
//   w1*v1+w2*v2 = (v1*b + v2*a)/(a*b)
// d==0: fold +1e-12 into d^2 (dominating weight, same interpolated value,
// no branch, pair product can't underflow).

#define NSTATIONS 512
#define TPB 128
#define PTS 2  // grid points per thread = one packed f32x2 lane

typedef unsigned long long u64;

__device__ __forceinline__ u64 f2_pack(float lo, float hi) {
    u64 r; asm("mov.b64 %0, {%1, %2};" : "=l"(r) : "f"(lo), "f"(hi)); return r;
}
__device__ __forceinline__ void f2_unpack(u64 a, float& lo, float& hi) {
    asm("mov.b64 {%0, %1}, %2;" : "=f"(lo), "=f"(hi) : "l"(a));
}
__device__ __forceinline__ u64 f2_add(u64 a, u64 b) {
    u64 r; asm("add.rn.f32x2 %0, %1, %2;" : "=l"(r) : "l"(a), "l"(b)); return r;
}
__device__ __forceinline__ u64 f2_mul(u64 a, u64 b) {
    u64 r; asm("mul.rn.f32x2 %0, %1, %2;" : "=l"(r) : "l"(a), "l"(b)); return r;
}
__device__ __forceinline__ u64 f2_fma(u64 a, u64 b, u64 c) {
    u64 r; asm("fma.rn.f32x2 %0, %1, %2, %3;" : "=l"(r) : "l"(a), "l"(b), "l"(c)); return r;
}
__device__ __forceinline__ float frcp(float a) {
    float r; asm("rcp.approx.f32 %0, %1;" : "=f"(r) : "f"(a)); return r;
}
__device__ __forceinline__ u64 f2_rcp(u64 a) {
    float lo, hi; f2_unpack(a, lo, hi);
    return f2_pack(frcp(lo), frcp(hi));
}

__global__ __launch_bounds__(TPB) void idw_kernel(
    const float* __restrict__ station_coords,  // (B, S, 2)
    const float* __restrict__ station_values,  // (B, S)
    const float* __restrict__ grid_points,     // (B, P, 2)
    float* __restrict__ out,                   // (B, P)
    int P)
{
    // Duplicated/negated station data: one LDS.64 -> ready packed broadcast
    __shared__ u64 sh_nx[NSTATIONS];  // (-x, -x)
    __shared__ u64 sh_ny[NSTATIONS];  // (-y, -y)
    __shared__ u64 sh_vv[NSTATIONS];  // ( v,  v)

    const int base = (blockIdx.x * TPB + threadIdx.x) * PTS;  // global point id
    const int b = base / P;  // TPB*PTS=256 divides P -> no block straddles batches

    const float* sc = station_coords + (size_t)b * NSTATIONS * 2;
    const float* sv = station_values + (size_t)b * NSTATIONS;

    for (int s = threadIdx.x; s < NSTATIONS; s += TPB) {
        float2 c = reinterpret_cast<const float2*>(sc)[s];
        float v = sv[s];
        sh_nx[s] = f2_pack(-c.x, -c.x);
        sh_ny[s] = f2_pack(-c.y, -c.y);
        sh_vv[s] = f2_pack(v, v);
    }
    __syncthreads();

    // Load 2 grid points = 1 x float4 (coalesced, 16B/thread)
    float4 a0 = reinterpret_cast<const float4*>(
        grid_points + (size_t)base * 2)[0];

    const u64 gx = f2_pack(a0.x, a0.z);
    const u64 gy = f2_pack(a0.y, a0.w);

    const u64 eps2 = f2_pack(1e-12f, 1e-12f);
    u64 ws = 0ull;  // packed (0.0f, 0.0f)
    u64 vs = 0ull;

    #pragma unroll 4
    for (int s = 0; s < NSTATIONS; s += 2) {
        u64 nx1 = sh_nx[s],     ny1 = sh_ny[s],     v1 = sh_vv[s];
        u64 nx2 = sh_nx[s + 1], ny2 = sh_ny[s + 1], v2 = sh_vv[s + 1];

        u64 dx1 = f2_add(gx, nx1);
        u64 dy1 = f2_add(gy, ny1);
        u64 da  = f2_fma(dy1, dy1, eps2);
        da      = f2_fma(dx1, dx1, da);        // a = d2 of station 1
        u64 dx2 = f2_add(gx, nx2);
        u64 dy2 = f2_add(gy, ny2);
        u64 db  = f2_fma(dy2, dy2, eps2);
        db      = f2_fma(dx2, dx2, db);        // b = d2 of station 2
        u64 sum  = f2_add(da, db);             // a + b
        u64 prod = f2_mul(da, db);             // a * b
        u64 num  = f2_mul(v1, db);
        num      = f2_fma(v2, da, num);        // v1*b + v2*a
        u64 r    = f2_rcp(prod);               // 2x MUFU.RCP per 2 stations
        ws = f2_fma(sum, r, ws);
        vs = f2_fma(num, r, vs);
    }

    float w0, w1, n0, n1;
    f2_unpack(ws, w0, w1);
    f2_unpack(vs, n0, n1);

    float2 r;
    r.x = n0 * frcp(w0);
    r.y = n1 * frcp(w1);
    reinterpret_cast<float2*>(out + (size_t)base)[0] = r;  // out is (B,P) flat
}

extern "C" void kernel_launch(void* const* d_in, const int* in_sizes, int n_in,
                              void* d_out, int out_size) {
    const float* station_coords = (const float*)d_in[0];  // (B,S,2)
    const float* station_values = (const float*)d_in[1];  // (B,S)
    const float* grid_points    = (const float*)d_in[2];  // (B,P,2)
    float* out = (float*)d_out;

    const int S = NSTATIONS;                 // 512 per problem spec
    const int B = in_sizes[1] / S;           // 2
    const int P = in_sizes[2] / (B * 2);     // 131072

    const int total_points = B * P;                    // 262144
    const int blocks = total_points / (TPB * PTS);     // 1024 blocks, 4096 warps
    idw_kernel<<<blocks, TPB>>>(station_coords, station_values, grid_points,
                                out, P);
}

// round 4
// speedup vs baseline: 1.5058x; 1.0071x over previous
#include <cuda_runtime.h>
#include <cuda_bf16.h>

// IDW interpolation, POWER=2:  w = 1/d^2 (sqrt cancels).
//
// Round 4: round 3 was fma-pipe-roofline-capable (~26us of fma work) but ran
// at issue=67.7%, occ=29.5% because total warps were capped at 4096 by
// points/(warp*2). Fix: STATION SPLIT x4 -- each block processes 128 of the
// 512 stations for its grid points, writing partial (sum_w, sum_wv) to a
// __device__ scratch; a small finalize kernel sums the 4 partials and
// divides. 16384 warps (~28/SMSP). Also: station pair data staged as 3x16B
// -> 3 LDS.128 per pair-body instead of 6 LDS.64.
//
// Pairing identity for d2 values a,b (1 MUFU.RCP per 2 stations per point):
//   w1+w2       = (a+b)/(a*b)
//   w1*v1+w2*v2 = (v1*b + v2*a)/(a*b)
// d==0: fold +1e-12 into d^2 (dominating weight, same interpolated value,
// no branch, pair product can't underflow).

#define NSTATIONS 512
#define SPLITS 4
#define S_SPLIT (NSTATIONS / SPLITS)   // 128 stations per block
#define PAIRS (S_SPLIT / 2)            // 64 pair-bodies per block
#define TPB 128
#define NPACKS 131072                  // total points / 2

typedef unsigned long long u64;

// Partials: (ws_lo, ws_hi, vs_lo, vs_hi) per point-pack per split. 8 MB.
__device__ float4 g_partial[SPLITS][NPACKS];

__device__ __forceinline__ u64 f2_pack(float lo, float hi) {
    u64 r; asm("mov.b64 %0, {%1, %2};" : "=l"(r) : "f"(lo), "f"(hi)); return r;
}
__device__ __forceinline__ void f2_unpack(u64 a, float& lo, float& hi) {
    asm("mov.b64 {%0, %1}, %2;" : "=f"(lo), "=f"(hi) : "l"(a));
}
__device__ __forceinline__ u64 f2_add(u64 a, u64 b) {
    u64 r; asm("add.rn.f32x2 %0, %1, %2;" : "=l"(r) : "l"(a), "l"(b)); return r;
}
__device__ __forceinline__ u64 f2_mul(u64 a, u64 b) {
    u64 r; asm("mul.rn.f32x2 %0, %1, %2;" : "=l"(r) : "l"(a), "l"(b)); return r;
}
__device__ __forceinline__ u64 f2_fma(u64 a, u64 b, u64 c) {
    u64 r; asm("fma.rn.f32x2 %0, %1, %2, %3;" : "=l"(r) : "l"(a), "l"(b), "l"(c)); return r;
}
__device__ __forceinline__ float frcp(float a) {
    float r; asm("rcp.approx.f32 %0, %1;" : "=f"(r) : "f"(a)); return r;
}
__device__ __forceinline__ u64 f2_rcp(u64 a) {
    float lo, hi; f2_unpack(a, lo, hi);
    return f2_pack(frcp(lo), frcp(hi));
}

__global__ __launch_bounds__(TPB) void idw_main(
    const float* __restrict__ station_coords,  // (B, S, 2)
    const float* __restrict__ station_values,  // (B, S)
    const float* __restrict__ grid_points,     // (B, P, 2)
    int P)
{
    // Per station pair p, 6 u64 slots (3 x 16B, LDS.128 each):
    //   [0]=(-x1,-x1) [1]=(-y1,-y1) [2]=(-x2,-x2) [3]=(-y2,-y2) [4]=(v1,v1) [5]=(v2,v2)
    __shared__ u64 sh[PAIRS * 6];

    const int pack  = blockIdx.x * TPB + threadIdx.x;   // 0..NPACKS-1
    const int split = blockIdx.y;                        // 0..3
    const int base  = pack * 2;                          // global point id
    const int b     = base / P;   // TPB*2=256 divides P: block stays in one batch

    // Stage this split's 128 stations: one station per thread.
    {
        const int t = threadIdx.x;  // == station index within split
        const float2 c = reinterpret_cast<const float2*>(
            station_coords + ((size_t)b * NSTATIONS + split * S_SPLIT) * 2)[t];
        const float v = station_values[(size_t)b * NSTATIONS + split * S_SPLIT + t];
        const int p = t >> 1, w = t & 1;
        sh[p * 6 + w * 2 + 0] = f2_pack(-c.x, -c.x);
        sh[p * 6 + w * 2 + 1] = f2_pack(-c.y, -c.y);
        sh[p * 6 + 4 + w]     = f2_pack(v, v);
    }
    __syncthreads();

    // Load 2 grid points = 1 float4 (coalesced)
    const float4 a0 = reinterpret_cast<const float4*>(grid_points)[pack];
    const u64 gx = f2_pack(a0.x, a0.z);
    const u64 gy = f2_pack(a0.y, a0.w);

    const u64 eps2 = f2_pack(1e-12f, 1e-12f);
    u64 ws = 0ull, vs = 0ull;  // packed (0,0)

    const ulonglong2* sh2 = reinterpret_cast<const ulonglong2*>(sh);

    #pragma unroll 4
    for (int p = 0; p < PAIRS; p++) {
        ulonglong2 c1 = sh2[p * 3 + 0];  // (nx1, ny1)  LDS.128
        ulonglong2 c2 = sh2[p * 3 + 1];  // (nx2, ny2)  LDS.128
        ulonglong2 vv = sh2[p * 3 + 2];  // (vv1, vv2)  LDS.128

        u64 dx1 = f2_add(gx, c1.x);
        u64 dy1 = f2_add(gy, c1.y);
        u64 da  = f2_fma(dy1, dy1, eps2);
        da      = f2_fma(dx1, dx1, da);        // a = d2 of station 1
        u64 dx2 = f2_add(gx, c2.x);
        u64 dy2 = f2_add(gy, c2.y);
        u64 db  = f2_fma(dy2, dy2, eps2);
        db      = f2_fma(dx2, dx2, db);        // b = d2 of station 2
        u64 sum  = f2_add(da, db);             // a + b
        u64 prod = f2_mul(da, db);             // a * b
        u64 num  = f2_mul(vv.x, db);
        num      = f2_fma(vv.y, da, num);      // v1*b + v2*a
        u64 r    = f2_rcp(prod);               // 2x MUFU.RCP per 2 stations
        ws = f2_fma(sum, r, ws);
        vs = f2_fma(num, r, vs);
    }

    float w0, w1, n0, n1;
    f2_unpack(ws, w0, w1);
    f2_unpack(vs, n0, n1);
    g_partial[split][pack] = make_float4(w0, w1, n0, n1);
}

__global__ __launch_bounds__(256) void idw_finalize(float* __restrict__ out)
{
    const int pack = blockIdx.x * 256 + threadIdx.x;  // 0..NPACKS-1
    float4 p0 = g_partial[0][pack];
    float4 p1 = g_partial[1][pack];
    float4 p2 = g_partial[2][pack];
    float4 p3 = g_partial[3][pack];
    float ws0 = (p0.x + p1.x) + (p2.x + p3.x);
    float ws1 = (p0.y + p1.y) + (p2.y + p3.y);
    float vs0 = (p0.z + p1.z) + (p2.z + p3.z);
    float vs1 = (p0.w + p1.w) + (p2.w + p3.w);
    float2 r;
    r.x = vs0 / ws0;
    r.y = vs1 / ws1;
    reinterpret_cast<float2*>(out)[pack] = r;
}

extern "C" void kernel_launch(void* const* d_in, const int* in_sizes, int n_in,
                              void* d_out, int out_size) {
    const float* station_coords = (const float*)d_in[0];  // (B,S,2)
    const float* station_values = (const float*)d_in[1];  // (B,S)
    const float* grid_points    = (const float*)d_in[2];  // (B,P,2)
    float* out = (float*)d_out;

    const int S = NSTATIONS;                 // 512 per problem spec
    const int B = in_sizes[1] / S;           // 2
    const int P = in_sizes[2] / (B * 2);     // 131072

    dim3 grid(NPACKS / TPB, SPLITS);         // (1024, 4) = 4096 blocks
    idw_main<<<grid, TPB>>>(station_coords, station_values, grid_points, P);
    idw_finalize<<<NPACKS / 256, 256>>>(out);
}